// round 9
// baseline (speedup 1.0000x reference)
#include <cuda_runtime.h>
#include <cuda_bf16.h>

// Problem constants (static per reference)
#define BS 4
#define H0 64
#define W0 64
#define L0 (H0 * W0)            // 4096
#define ANCHOR_NUM 64

#define NUM_COPY_BLOCKS 2048
#define THREADS 512
#define CELLS_PER_THREAD (L0 / THREADS)   // 8
#define NWARPS (THREADS / 32)             // 16

__device__ __forceinline__ float4 ldcs4(const float4* p) {
    float4 v;
    asm volatile("ld.global.cs.v4.f32 {%0,%1,%2,%3}, [%4];"
                 : "=f"(v.x), "=f"(v.y), "=f"(v.z), "=f"(v.w) : "l"(p));
    return v;
}
__device__ __forceinline__ void stcs4(float4* p, float4 v) {
    asm volatile("st.global.cs.v4.f32 [%0], {%1,%2,%3,%4};"
                 :: "l"(p), "f"(v.x), "f"(v.y), "f"(v.z), "f"(v.w) : "memory");
}

// Fused kernel:
//   blocks 0..BS-1      : per-batch anchor extraction (scatter + NMS + select)
//   blocks BS..BS+NCB-1 : float4 streaming passthrough copy of conf_matrix
__global__ void __launch_bounds__(THREADS)
ae_fused_kernel(const float*  __restrict__ conf,
                const float*  __restrict__ mconf,
                const int*    __restrict__ b_ids,
                const int*    __restrict__ i_ids,
                const int*    __restrict__ j_ids,
                float*        __restrict__ out,
                int nconf, int M, int anchors_elems) {
    const int t = threadIdx.x;

    if (blockIdx.x >= BS) {
        // ---------------- bulk copy path ----------------
        const int cb = blockIdx.x - BS;
        const long long n4 = (long long)nconf >> 2;          // float4 count
        const float4* __restrict__ src = (const float4*)conf;
        float4* __restrict__ dst = (float4*)(out + anchors_elems);
        const long long stride = (long long)NUM_COPY_BLOCKS * THREADS;
        long long idx = (long long)cb * THREADS + t;

        if (n4 == stride * 16) {
            // exact fit: 2 x (batch 8 LDG.128 then 8 STG.128)
#pragma unroll
            for (int half = 0; half < 2; half++) {
                const long long base = idx + (long long)half * 8 * stride;
                float4 v[8];
#pragma unroll
                for (int u = 0; u < 8; u++)
                    v[u] = ldcs4(src + base + (long long)u * stride);
#pragma unroll
                for (int u = 0; u < 8; u++)
                    stcs4(dst + base + (long long)u * stride, v[u]);
            }
        } else {
            for (; idx < n4; idx += stride)
                stcs4(dst + idx, ldcs4(src + idx));
        }
        return;
    }

    // ---------------- anchor path (block b) ----------------
    __shared__ int   win_s[L0];          // winner match index per cell (-1 empty)
    __shared__ float conf_s[L0];
    __shared__ int   list_s[ANCHOR_NUM];
    __shared__ int   warp_sums[NWARPS];
    __shared__ int   total_s;

    const int b = blockIdx.x;

    // init winners
#pragma unroll
    for (int k = 0; k < CELLS_PER_THREAD; k++)
        win_s[t * CELLS_PER_THREAD + k] = -1;
    __syncthreads();

    // private scatter: last-write-wins == max match index wins
    for (int m = t; m < M; m += THREADS) {
        if (b_ids[m] == b)
            atomicMax(&win_s[i_ids[m]], m);
    }
    __syncthreads();

    // stage confidences
#pragma unroll
    for (int k = 0; k < CELLS_PER_THREAD; k++) {
        int c  = t * CELLS_PER_THREAD + k;
        int wn = win_s[c];
        conf_s[c] = (wn >= 0) ? mconf[wn] : 0.0f;
    }
    __syncthreads();

    // NMS mask: local max vs right/down/down-right (pad = 0), conf > 0
    int mbits = 0, cnt_loc = 0;
#pragma unroll
    for (int k = 0; k < CELLS_PER_THREAD; k++) {
        int c = t * CELLS_PER_THREAD + k;
        int h = c >> 6;
        int w = c & 63;
        float v  = conf_s[c];
        float r  = (w < W0 - 1)               ? conf_s[c + 1]      : 0.0f;
        float d  = (h < H0 - 1)               ? conf_s[c + W0]     : 0.0f;
        float dr = (w < W0 - 1 && h < H0 - 1) ? conf_s[c + W0 + 1] : 0.0f;
        bool mm = (v > 0.0f) && (v >= r) && (v >= d) && (v >= dr);
        mbits |= ((int)mm) << k;
        cnt_loc += (int)mm;
    }

    // block-wide inclusive scan over per-thread counts (16 warps)
    const int lane = t & 31;
    const int wid  = t >> 5;
    int x = cnt_loc;
#pragma unroll
    for (int o = 1; o < 32; o <<= 1) {
        int y = __shfl_up_sync(0xFFFFFFFFu, x, o);
        if (lane >= o) x += y;
    }
    if (lane == 31) warp_sums[wid] = x;
    __syncthreads();
    // Stage 2: ALL 32 lanes of warp 0 participate in the shuffles
    // (lanes >= NWARPS carry 0); only the first NWARPS lanes write back.
    if (wid == 0) {
        int s = (lane < NWARPS) ? warp_sums[lane] : 0;
#pragma unroll
        for (int o = 1; o < NWARPS; o <<= 1) {
            int y = __shfl_up_sync(0xFFFFFFFFu, s, o);
            if (lane >= o) s += y;
        }
        if (lane < NWARPS) warp_sums[lane] = s;
        if (lane == NWARPS - 1) total_s = s;
    }
    __syncthreads();

    int excl = (x - cnt_loc) + (wid > 0 ? warp_sums[wid - 1] : 0);

    // first ANCHOR_NUM surviving cells in raster order
#pragma unroll
    for (int k = 0; k < CELLS_PER_THREAD; k++) {
        if (mbits & (1 << k)) {
            if (excl < ANCHOR_NUM) list_s[excl] = t * CELLS_PER_THREAD + k;
            excl++;
        }
    }
    __syncthreads();

    const int cnt = total_s;
    if (t < ANCHOR_NUM) {
        float4 a = make_float4(0.0f, 0.0f, 0.0f, 0.0f);
        if (cnt > 0) {
            int idx = t % cnt;               // arange(64) % cnt
            int sel = list_s[idx];
            int j   = j_ids[win_s[sel]];
            a.x = (float)(sel >> 6);
            a.y = (float)(sel & 63);
            a.z = (float)(j >> 6);
            a.w = (float)(j & 63);
        }
        reinterpret_cast<float4*>(out)[b * ANCHOR_NUM + t] = a;
    }
}

extern "C" void kernel_launch(void* const* d_in, const int* in_sizes, int n_in,
                              void* d_out, int out_size) {
    const float* conf  = (const float*)d_in[0];   // [BS, L0, L1]
    const float* mconf = (const float*)d_in[1];   // [M]
    const int*   b_ids = (const int*)d_in[2];     // [M]
    const int*   i_ids = (const int*)d_in[3];     // [M]
    const int*   j_ids = (const int*)d_in[4];     // [M]
    float* out = (float*)d_out;

    const int nconf = in_sizes[0];
    const int M     = in_sizes[1];
    const int anchors_elems = out_size - nconf;   // expected 1024

    ae_fused_kernel<<<BS + NUM_COPY_BLOCKS, THREADS>>>(
        conf, mconf, b_ids, i_ids, j_ids, out, nconf, M, anchors_elems);
}